// round 16
// baseline (speedup 1.0000x reference)
#include <cuda_runtime.h>
#include <math.h>

#define B   32
#define E   512
#define H   512
#define H4  2048
#define S   64
#define T   48
#define VT  32000
#define TL  (T-1)
#define VB  640
#define NCHUNK (VT/VB)
#define NBLK 128

#define PIDX(h,b) ((((h)>>1)<<6) + ((b)<<1) + ((h)&1))
typedef unsigned long long ull;

__device__ __align__(128) float g_x[S*E*B];
__device__ __align__(128) float g_y[T*E*B];
__device__ __align__(128) float g_zx0[S*H4*B];
__device__ __align__(128) float g_zy [T*H4*B];
__device__ __align__(128) float g_h1seq[S*H*B];
__device__ __align__(128) float g_h2seq[S*H*B];
__device__ __align__(128) float g_ebsh[B*S*H];
__device__ __align__(128) float g_ebhs[B*H*S];
__device__ __align__(128) float g_F[B*H*S];
__device__ __align__(128) float g_A[H*B];
__device__ __align__(128) float g_zcy[H*B];
__device__ __align__(128) float g_scores[B*S];
__device__ __align__(128) float g_c0[H*B];
__device__ __align__(128) float g_c1[H*B];
__device__ __align__(128) float g_dh0a[H*B];
__device__ __align__(128) float g_dh0b[H*B];
__device__ __align__(128) float g_dh1a[H*B];
__device__ __align__(128) float g_dh1b[H*B];
__device__ __align__(128) float g_zero[H*B];
__device__ __align__(128) float g_decout[T*H*B];
__device__ __align__(128) float g_pmax[TL*NCHUNK*B];
__device__ __align__(128) float g_psum[TL*NCHUNK*B];
__device__ __align__(128) float g_tgtl[TL*B];
__device__ __align__(128) float g_lp[TL*B];

__device__ __forceinline__ void fma2(ull& a, ull w, ull u) {
    asm("fma.rn.f32x2 %0, %1, %2, %3;" : "=l"(a) : "l"(w), "l"(u), "l"(a));
}
__device__ __forceinline__ float sum2(ull v) {
    float lo, hi;
    asm("mov.b64 {%0, %1}, %2;" : "=f"(lo), "=f"(hi) : "l"(v));
    return lo + hi;
}

// ---- tree grid barriers (monotonic counters; proven R14 mechanics) ----
__device__ __align__(128) unsigned g_leaf[256];    // decoder: 8 leaves x 128B
__device__ __align__(128) unsigned g_leafE0[128];  // encoder grp0: 4 leaves
__device__ __align__(128) unsigned g_leafE1[128];  // encoder grp1: 4 leaves
__device__ unsigned g_root, g_rootE0, g_rootE1;
__device__ volatile unsigned g_gen, g_genE0, g_genE1;

__device__ __forceinline__ void tbar(unsigned* leaf, int leafmask,
                                     unsigned* root, unsigned rootmask,
                                     volatile unsigned* gen) {
    __syncthreads();
    if (threadIdx.x == 0) {
        unsigned old = *gen;
        __threadfence();
        unsigned a = atomicAdd(&leaf[(blockIdx.x & leafmask) << 5], 1u);
        bool rel = false;
        if ((a & 15) == 15) {
            unsigned r = atomicAdd(root, 1u);
            if ((r & rootmask) == rootmask) {
                __threadfence();
                *gen = old + 1;
                rel = true;
            }
        }
        if (!rel)
            while (*gen == old) __nanosleep(64);
        __threadfence();
    }
    __syncthreads();
}
__device__ __forceinline__ void wait_ge(volatile unsigned* gen, unsigned target) {
    __syncthreads();
    if (threadIdx.x == 0) {
        while (*gen < target) __nanosleep(64);
        __threadfence();
    }
    __syncthreads();
}

// ---- init: embeddings + state/counter zeroing in ONE launch ----
__global__ void k_init(const int* __restrict__ src, const int* __restrict__ tgt,
                       const float* __restrict__ semb, const float* __restrict__ temb) {
    int n = blockIdx.x, b = blockIdx.y, tid = threadIdx.x;
    if (n < S + T) {
        const float* e; float* d;
        if (n < S) { e = semb + (size_t)src[n * B + b] * E; d = g_x + (size_t)n * E * B; }
        else { int m = n - S; e = temb + (size_t)tgt[m * B + b] * E; d = g_y + (size_t)m * E * B; }
        for (int k = tid; k < E; k += 128) d[PIDX(k, b)] = e[k];
    } else {
        for (int i = b * 128 + tid; i < H * B; i += 32 * 128) {
            g_c0[i] = 0.f; g_c1[i] = 0.f; g_zero[i] = 0.f;
        }
        if (b == 0) {
            if (tid < 128) {
                g_leaf[tid] = 0u; g_leaf[tid + 128] = 0u;
                g_leafE0[tid] = 0u; g_leafE1[tid] = 0u;
            }
            if (tid == 0) {
                g_root = 0u; g_rootE0 = 0u; g_rootE1 = 0u;
                g_gen = 0u; g_genE0 = 0u; g_genE1 = 0u;
            }
        }
    }
}

// both pre-GEMMs in ONE launch; grid (32, T+S). 48KB smem, 4 blocks/SM.
__global__ void __launch_bounds__(256) k_preB(
        const float* __restrict__ Wd, const float* __restrict__ bd,
        const float* __restrict__ We, const float* __restrict__ be) {
    extern __shared__ __align__(16) float smp[];
    float* su = smp;
    float* wt = smp + 4096;
    const ull* su2 = (const ull*)su;
    const int tid = threadIdx.x, lane = tid & 31, warp = tid >> 5;
    const int by = blockIdx.y;
    const float *W, *bias, *U; float* Z; int ldw, n;
    if (by < T) { W = Wd; bias = bd; U = g_y; Z = g_zy;  ldw = E + H; n = by; }
    else        { W = We; bias = be; U = g_x; Z = g_zx0; ldw = E;     n = by - T; }
    const int o0 = blockIdx.x * 64;
    ull acc2[8] = {0ull,0ull,0ull,0ull,0ull,0ull,0ull,0ull};
    for (int kc = 0; kc < 4; kc++) {
        __syncthreads();
        {
            const float4* src = (const float4*)(U + ((size_t)n * 512 + kc * 128) * B);
            #pragma unroll
            for (int i = tid; i < 1024; i += 256) ((float4*)su)[i] = src[i];
            #pragma unroll
            for (int q = 0; q < 8; q++) {
                int f4 = q * 256 + tid;
                ((float4*)wt)[f4] = *(const float4*)(
                    W + (size_t)(o0 + (f4 >> 5)) * ldw + kc * 128 + (f4 & 31) * 4);
            }
        }
        __syncthreads();
        #pragma unroll 4
        for (int kk = 0; kk < 128; kk += 4) {
            ull u01 = su2[(kk >> 1) * 32 + lane];
            ull u23 = su2[((kk >> 1) + 1) * 32 + lane];
            #pragma unroll
            for (int r = 0; r < 8; r++) {
                ulonglong2 wv = *(const ulonglong2*)(wt + (warp * 8 + r) * 128 + kk);
                fma2(acc2[r], wv.x, u01);
                fma2(acc2[r], wv.y, u23);
            }
        }
    }
    #pragma unroll
    for (int r = 0; r < 8; r++)
        Z[((size_t)n * H4 + o0 + warp * 8 + r) * B + lane] =
            sum2(acc2[r]) + bias[o0 + warp * 8 + r];
}

// LSTM cell (known-good): 2 groups of 8 warps, smem-staged u
template<int HPB>
__device__ __forceinline__ void cellS(
        int blk, const float* __restrict__ zpre, const float* __restrict__ bias,
        const float* sW1, const float* sW2,
        const float* __restrict__ u1, const float* __restrict__ u2,
        float* __restrict__ C, float* __restrict__ Hout, float* su, float* sz) {
    constexpr int NR = 4 * HPB, RPW = NR / 8;
    const int tid = threadIdx.x, lane = tid & 31, w = tid >> 5;
    const int g = w >> 3, wi = w & 7;
    const int h0 = blk * HPB;
    const bool dual = (sW2 != nullptr);
    const float* sW = (dual && g) ? sW2 : sW1;
    const float* u  = (dual && g) ? u2  : u1;
    const int Kbase  = dual ? 0 : g * 256;
    const int nchunk = dual ? 4 : 2;
    float* sbuf = su + g * (128 * B);
    const ull* sb2 = (const ull*)sbuf;
    const int gt = tid & 255;
    ull acc[RPW][2];
    #pragma unroll
    for (int j = 0; j < RPW; j++) { acc[j][0] = 0ull; acc[j][1] = 0ull; }
    for (int c = 0; c < nchunk; c++) {
        const float4* src = (const float4*)(u + (size_t)(Kbase + c * 128) * B);
        float4* dst = (float4*)sbuf;
        #pragma unroll
        for (int q = 0; q < 4; q++) dst[gt + 256 * q] = src[gt + 256 * q];
        __syncthreads();
        const int kofs = Kbase + c * 128;
        #pragma unroll 8
        for (int kk = 0; kk < 128; kk += 4) {
            ull u01 = sb2[(kk >> 1) * 32 + lane];
            ull u23 = sb2[(kk >> 1) * 32 + 32 + lane];
            #pragma unroll
            for (int j = 0; j < RPW; j++) {
                int r = wi * RPW + j;
                ulonglong2 wv = *(const ulonglong2*)(sW + r * 512 + kofs + kk);
                fma2(acc[j][0], wv.x, u01);
                fma2(acc[j][1], wv.y, u23);
            }
        }
        __syncthreads();
    }
    #pragma unroll
    for (int j = 0; j < RPW; j++) {
        int r = wi * RPW + j;
        int o = (r / HPB) * H + h0 + (r % HPB);
        float v = sum2(acc[j][0]) + sum2(acc[j][1]);
        if (g == 0) v += zpre ? zpre[(size_t)o * B + lane] : bias[o];
        sz[(g * NR + r) * 32 + lane] = v;
    }
    __syncthreads();
    if (tid < HPB * 32) {
        int hh = tid >> 5, b = tid & 31;
        float z[4];
        #pragma unroll
        for (int jg = 0; jg < 4; jg++) {
            int r = jg * HPB + hh;
            z[jg] = sz[r * 32 + b] + sz[(NR + r) * 32 + b];
        }
        float ig = 1.f / (1.f + expf(-z[0]));
        float fg = 1.f / (1.f + expf(-z[1]));
        float gg = tanhf(z[2]);
        float og = 1.f / (1.f + expf(-z[3]));
        int h = h0 + hh;
        float c2 = fg * C[h * B + b] + ig * gg;
        C[h * B + b]     = c2;
        Hout[PIDX(h, b)] = og * tanhf(c2);
    }
    __syncthreads();
}

// encoder: group0 (blocks 0-63) layer0 with own 64-wide tree barrier;
// group1 (64-127) layer1 follows group0's generation counter one step behind.
__global__ void __launch_bounds__(512) k_encoder(
        const float* __restrict__ eWhh0, const float* __restrict__ eWih1,
        const float* __restrict__ eWhh1, const float* __restrict__ eb1) {
    extern __shared__ __align__(16) float sm[];
    float* su = sm;
    float* sz = sm + 8192;
    float* sw = sm + 10240;
    const int blk = blockIdx.x, tid = threadIdx.x;
    if (blk < 64) {
        for (int i = tid; i < 32 * 128; i += 512) {
            int r = i >> 7, c4 = i & 127;
            int o = (r >> 3) * H + blk * 8 + (r & 7);
            ((float4*)sw)[i] = *(const float4*)(eWhh0 + (size_t)o * H + c4 * 4);
        }
        __syncthreads();
        for (int s = 0; s < S; s++) {
            const float* hp = s ? g_h1seq + (size_t)(s - 1) * H * B : g_zero;
            cellS<8>(blk, g_zx0 + (size_t)s * H4 * B, nullptr, sw, nullptr,
                     hp, nullptr, g_c0, g_h1seq + (size_t)s * H * B, su, sz);
            tbar(g_leafE0, 3, &g_rootE0, 3, &g_genE0);
        }
    } else {
        int b2 = blk - 64;
        for (int i = tid; i < 32 * 128; i += 512) {
            int r = i >> 7, c4 = i & 127;
            int o = (r >> 3) * H + b2 * 8 + (r & 7);
            ((float4*)sw)[i]           = *(const float4*)(eWih1 + (size_t)o * H + c4 * 4);
            ((float4*)(sw + 16384))[i] = *(const float4*)(eWhh1 + (size_t)o * H + c4 * 4);
        }
        __syncthreads();
        for (int s = 0; s < S; s++) {
            wait_ge(&g_genE0, (unsigned)(s + 1));
            const float* hp = s ? g_h2seq + (size_t)(s - 1) * H * B : g_zero;
            cellS<8>(b2, nullptr, eb1, sw, sw + 16384,
                     g_h1seq + (size_t)s * H * B, hp,
                     g_c1, g_h2seq + (size_t)s * H * B, su, sz);
            tbar(g_leafE1, 3, &g_rootE1, 3, &g_genE1);
        }
        for (int idx = b2; idx < S * B; idx += 64) {
            int s = idx >> 5, b = idx & 31;
            for (int h = tid; h < H; h += 512) {
                float v = g_h2seq[(size_t)s * H * B + PIDX(h, b)];
                g_ebsh[((size_t)b * S + s) * H + h] = v;
                g_ebhs[((size_t)b * H + h) * S + s] = v;
            }
        }
    }
}

__global__ void __launch_bounds__(512) k_decoder(
        const float* __restrict__ dWih0, const float* __restrict__ dWhh0,
        const float* __restrict__ dWih1, const float* __restrict__ dWhh1,
        const float* __restrict__ db1,
        const float* __restrict__ Wht, const float* __restrict__ Wpt,
        const float* __restrict__ Wct, const int* __restrict__ elen) {
    extern __shared__ __align__(16) float sm[];
    float* su  = sm;            // 16384
    float* sz  = sm + 16384;    // 1024
    float* sWa = sm + 17408;    // 4 x 8192
    float* sWb = sWa + 8192;
    float* sWc = sWb + 8192;
    float* sWd = sWc + 8192;
    float* sy  = sWd + 8192;    // 512
    __shared__ float s_at[S];
    __shared__ float s_red[20];
    const int blk = blockIdx.x, tid = threadIdx.x, lane = tid & 31, w = tid >> 5;
    const ull* su2 = (const ull*)su;

    // ---- prologue: F[b,h,s] = Wct[h,:H] . ebhs[b,:,s] (folded k_Fpre) ----
    {
        float* se  = sm;                 // 8192 floats
        float* swd = sm + 8192;          // 16384 floats
        const ull* se2  = (const ull*)se;
        const ull* swd2 = (const ull*)swd;
        for (int task = blk; task < 256; task += NBLK) {
            int hc = task >> 5, b = task & 31;
            ull acc2[4] = {0ull,0ull,0ull,0ull};
            for (int kc = 0; kc < 4; kc++) {
                __syncthreads();
                const float4* src = (const float4*)(g_ebhs + ((size_t)b * H + kc * 128) * S);
                for (int i = tid; i < 2048; i += 512) ((float4*)se)[i] = src[i];
                for (int i4 = tid; i4 < 2048; i4 += 512) {
                    int row = i4 >> 5, c4 = i4 & 31;
                    float4 v = *(const float4*)(Wct + (size_t)(hc * 64 + row) * 1024 + kc * 128 + c4 * 4);
                    float2* dp = (float2*)(swd + (row * 128 + c4 * 4) * 2);
                    dp[0] = make_float2(v.x, v.x); dp[1] = make_float2(v.y, v.y);
                    dp[2] = make_float2(v.z, v.z); dp[3] = make_float2(v.w, v.w);
                }
                __syncthreads();
                #pragma unroll 4
                for (int kk = 0; kk < 128; kk++) {
                    ull u = se2[kk * 32 + lane];
                    #pragma unroll
                    for (int r = 0; r < 4; r++)
                        fma2(acc2[r], swd2[(w * 4 + r) * 128 + kk], u);
                }
            }
            #pragma unroll
            for (int r = 0; r < 4; r++) {
                int h = hc * 64 + w * 4 + r;
                ((ull*)(g_F + ((size_t)b * H + h) * S))[lane] = acc2[r];
            }
        }
        __syncthreads();
    }

    for (int i = tid; i < 2048; i += 512) {
        int r = i >> 7, c4 = i & 127;
        int o = (r >> 2) * H + blk * 4 + (r & 3);
        ((float4*)sWa)[i] = *(const float4*)(dWih0 + (size_t)o * (E + H) + E + c4 * 4);
        ((float4*)sWb)[i] = *(const float4*)(dWhh0 + (size_t)o * H + c4 * 4);
        ((float4*)sWc)[i] = *(const float4*)(dWih1 + (size_t)o * H + c4 * 4);
        ((float4*)sWd)[i] = *(const float4*)(dWhh1 + (size_t)o * H + c4 * 4);
    }
    __syncthreads();
    for (int t = 0; t < T; t++) {
        const float* htp = t ? g_decout + (size_t)(t - 1) * H * B : g_zero;
        const float* h0p = t ? (((t - 1) & 1) ? g_dh0b : g_dh0a)
                             : g_h1seq + (size_t)(S - 1) * H * B;
        float* h0c = (t & 1) ? g_dh0b : g_dh0a;
        cellS<4>(blk, g_zy + (size_t)t * H4 * B, nullptr, sWa, sWb,
                 htp, h0p, g_c0, h0c, su, sz);
        tbar(g_leaf, 7, &g_root, 7, &g_gen);
        const float* h1p = t ? (((t - 1) & 1) ? g_dh1b : g_dh1a)
                             : g_h2seq + (size_t)(S - 1) * H * B;
        float* h1c = (t & 1) ? g_dh1b : g_dh1a;
        cellS<4>(blk, nullptr, db1, sWc, sWd, h0c, h1p, g_c1, h1c, su, sz);
        tbar(g_leaf, 7, &g_root, 7, &g_gen);
        // P3: distributed GEMV (A rows + zcy rows) + scores on blocks 0-31
        {
            const float4* src = (const float4*)h1c;
            #pragma unroll
            for (int i = tid; i < 4096; i += 512) ((float4*)su)[i] = src[i];
            if (blk < B) sy[tid] = h1c[PIDX(tid, blk)];
            __syncthreads();
            {
                int j = w >> 1, khalf = w & 1;
                int rid = blk * 8 + j;
                const float* Wrow = (rid < 512) ? (Wht + (size_t)rid * 512)
                                                : (Wct + (size_t)(rid - 512) * 1024 + 512);
                ull a0 = 0ull, a1 = 0ull;
                const int kb2 = khalf * 128;
                #pragma unroll 8
                for (int kk = 0; kk < 256; kk += 4) {
                    ull u01 = su2[(kb2 + (kk >> 1)) * 32 + lane];
                    ull u23 = su2[(kb2 + (kk >> 1) + 1) * 32 + lane];
                    ulonglong2 wv = *(const ulonglong2*)(Wrow + khalf * 256 + kk);
                    fma2(a0, wv.x, u01);
                    fma2(a1, wv.y, u23);
                }
                sz[w * 32 + lane] = sum2(a0) + sum2(a1);
            }
            __syncthreads();
            if (tid < 256) {
                int jj = tid >> 5, b = tid & 31;
                int rr = blk * 8 + jj;
                float v = sz[(2 * jj) * 32 + b] + sz[(2 * jj + 1) * 32 + b];
                if (rr < 512) g_A[rr * 32 + b] = Wpt[rr] * tanhf(v);
                else          g_zcy[(rr - 512) * 32 + b] = v;
            }
            if (blk < B) {
                int b = blk, el = elen[b];
                float4 uk[4];
                #pragma unroll
                for (int qq = 0; qq < 4; qq++) uk[qq] = *(const float4*)(sy + qq * 128 + lane * 4);
                #pragma unroll
                for (int si = 0; si < 4; si++) {
                    int s = w * 4 + si;
                    const float* er = g_ebsh + ((size_t)b * S + s) * H;
                    float v = 0.f;
                    #pragma unroll
                    for (int qq = 0; qq < 4; qq++) {
                        float4 ev = *(const float4*)(er + qq * 128 + lane * 4);
                        v += ev.x*uk[qq].x + ev.y*uk[qq].y + ev.z*uk[qq].z + ev.w*uk[qq].w;
                    }
                    #pragma unroll
                    for (int off = 16; off; off >>= 1)
                        v += __shfl_xor_sync(0xffffffffu, v, off);
                    if (lane == 0) g_scores[b * S + s] = (s < el) ? v : -INFINITY;
                }
            }
        }
        tbar(g_leaf, 7, &g_root, 7, &g_gen);
        // P4: pt + softmax*gauss + decout (blocks 0-31)
        if (blk < B) {
            int b = blk;
            float a = g_A[tid * 32 + b];
            #pragma unroll
            for (int off = 16; off; off >>= 1) a += __shfl_xor_sync(0xffffffffu, a, off);
            if (lane == 0) s_red[w] = a;
            __syncthreads();
            if (tid == 0) {
                float dd = 0.f;
                #pragma unroll
                for (int i = 0; i < 16; i++) dd += s_red[i];
                s_red[16] = (1.f / (1.f + expf(-dd))) * (float)elen[b];
            }
            __syncthreads();
            if (w == 0) {
                float pt = s_red[16];
                float v0 = g_scores[b * S + lane], v1 = g_scores[b * S + lane + 32];
                float mx = fmaxf(v0, v1);
                #pragma unroll
                for (int off = 16; off; off >>= 1)
                    mx = fmaxf(mx, __shfl_xor_sync(0xffffffffu, mx, off));
                float e0 = expf(v0 - mx), e1 = expf(v1 - mx);
                float smv = e0 + e1;
                #pragma unroll
                for (int off = 16; off; off >>= 1)
                    smv += __shfl_xor_sync(0xffffffffu, smv, off);
                float inv = 1.f / smv;
                float d0 = (float)lane - pt, d1 = (float)(lane + 32) - pt;
                s_at[lane]      = e0 * inv * expf(-d0 * d0 * (1.f / 50.f));
                s_at[lane + 32] = e1 * inv * expf(-d1 * d1 * (1.f / 50.f));
            }
            __syncthreads();
            {
                int h = tid;
                float f = g_zcy[h * 32 + b];
                const float4* Fr = (const float4*)(g_F + ((size_t)b * H + h) * S);
                #pragma unroll
                for (int s4 = 0; s4 < 16; s4++) {
                    float4 fv = Fr[s4];
                    f += s_at[s4*4+0]*fv.x + s_at[s4*4+1]*fv.y
                       + s_at[s4*4+2]*fv.z + s_at[s4*4+3]*fv.w;
                }
                g_decout[(size_t)t * H * B + PIDX(h, b)] = tanhf(f);
            }
        }
        tbar(g_leaf, 7, &g_root, 7, &g_gen);
    }
}

__global__ void __launch_bounds__(256) k_logits(const float* __restrict__ Wf,
                                                const int* __restrict__ target) {
    extern __shared__ __align__(16) float sm_[];
    float* sdec = sm_;
    float* wt   = sm_ + 512 * B;
    const ull* sd2 = (const ull*)sdec;
    __shared__ float rm[8][32], rs[8][32];
    const int t = blockIdx.y, c = blockIdx.x;
    const int tid = threadIdx.x, lane = tid & 31, warp = tid >> 5;
    {
        const float4* src = (const float4*)&g_decout[(size_t)t * H * B];
        #pragma unroll
        for (int i = tid; i < H * B / 4; i += 256) ((float4*)sdec)[i] = src[i];
    }
    __syncthreads();
    const int tgt = target[(t + 1) * B + lane];
    float m = -INFINITY, ss = 0.f;
    for (int rt = 0; rt < 10; rt++) {
        const int r0 = c * VB + rt * 64;
        ull acc2[8] = {0ull,0ull,0ull,0ull,0ull,0ull,0ull,0ull};
        for (int kc = 0; kc < 4; kc++) {
            __syncthreads();
            #pragma unroll
            for (int q = 0; q < 8; q++) {
                int f4 = q * 256 + tid;
                ((float4*)wt)[f4] = *(const float4*)(
                    Wf + (size_t)(r0 + (f4 >> 5)) * H + kc * 128 + (f4 & 31) * 4);
            }
            __syncthreads();
            const ull* ub2 = sd2 + kc * 2048;
            #pragma unroll 4
            for (int kk = 0; kk < 128; kk += 4) {
                ull u01 = ub2[(kk >> 1) * 32 + lane];
                ull u23 = ub2[(kk >> 1) * 32 + 32 + lane];
                #pragma unroll
                for (int r = 0; r < 8; r++) {
                    ulonglong2 wv = *(const ulonglong2*)(wt + (warp * 8 + r) * 128 + kk);
                    fma2(acc2[r], wv.x, u01);
                    fma2(acc2[r], wv.y, u23);
                }
            }
        }
        #pragma unroll
        for (int r = 0; r < 8; r++) {
            float x = sum2(acc2[r]);
            if (r0 + warp * 8 + r == tgt) g_tgtl[t * B + lane] = x;
            float nm = fmaxf(m, x);
            ss = ss * expf(m - nm) + expf(x - nm);
            m = nm;
        }
    }
    rm[warp][lane] = m; rs[warp][lane] = ss;
    __syncthreads();
    if (tid < 32) {
        float M = -INFINITY, SS = 0.f;
        #pragma unroll
        for (int w2 = 0; w2 < 8; w2++) {
            float wm = rm[w2][tid], wss = rs[w2][tid];
            float nm = fmaxf(M, wm);
            SS = SS * expf(M - nm) + wss * expf(wm - nm);
            M = nm;
        }
        g_pmax[((size_t)t * NCHUNK + c) * B + tid] = M;
        g_psum[((size_t)t * NCHUNK + c) * B + tid] = SS;
    }
}

__global__ void k_combine(const int* __restrict__ target) {
    const int t = blockIdx.x, b = threadIdx.x;
    float M = -INFINITY;
    for (int c = 0; c < NCHUNK; c++)
        M = fmaxf(M, g_pmax[((size_t)t * NCHUNK + c) * B + b]);
    float ss = 0.f;
    for (int c = 0; c < NCHUNK; c++)
        ss += g_psum[((size_t)t * NCHUNK + c) * B + b] *
              expf(g_pmax[((size_t)t * NCHUNK + c) * B + b] - M);
    float lse = M + logf(ss);
    float mask = (target[(t + 1) * B + b] != 0) ? 1.f : 0.f;
    g_lp[t * B + b] = mask * (g_tgtl[t * B + b] - lse);
}

__global__ void k_out(float* __restrict__ out) {
    const int b = threadIdx.x;
    float s = 0.f;
    for (int t = 0; t < TL; t++) s += g_lp[t * B + b];
    out[b] = s;
}

extern "C" void kernel_launch(void* const* d_in, const int* in_sizes, int n_in,
                              void* d_out, int out_size) {
    const int*   source = (const int*)d_in[0];
    const int*   target = (const int*)d_in[1];
    const int*   elen   = (const int*)d_in[2];
    const float* p3  = (const float*)d_in[3];
    const float* p4  = (const float*)d_in[4];
    const float* p5  = (const float*)d_in[5];
    const float* p6  = (const float*)d_in[6];
    const float* p7  = (const float*)d_in[7];
    const float* p8  = (const float*)d_in[8];
    const float* p9  = (const float*)d_in[9];
    const float* p10 = (const float*)d_in[10];
    const float* p11 = (const float*)d_in[11];
    const float* p12 = (const float*)d_in[12];
    const float* p13 = (const float*)d_in[13];
    const float* p14 = (const float*)d_in[14];
    const float* p15 = (const float*)d_in[15];
    const float* p16 = (const float*)d_in[16];
    const float* p17 = (const float*)d_in[17];
    const float* p18 = (const float*)d_in[18];
    const float* p19 = (const float*)d_in[19];
    const float* p20 = (const float*)d_in[20];
    float* out = (float*)d_out;

    cudaFuncSetAttribute(k_preB,    cudaFuncAttributeMaxDynamicSharedMemorySize, 49152);
    cudaFuncSetAttribute(k_encoder, cudaFuncAttributeMaxDynamicSharedMemorySize, 172032);
    cudaFuncSetAttribute(k_decoder, cudaFuncAttributeMaxDynamicSharedMemorySize, 202752);
    cudaFuncSetAttribute(k_logits,  cudaFuncAttributeMaxDynamicSharedMemorySize, 98304);

    k_init<<<dim3(S + T + 1, B), 128>>>(source, target, p3, p4);      // 1
    k_preB<<<dim3(32, S + T), 256, 49152>>>(p11, p13, p5, p7);        // 2
    k_encoder<<<NBLK, 512, 172032>>>(p6, p8, p9, p10);                // 3
    k_decoder<<<NBLK, 512, 202752>>>(p11, p12, p14, p15, p16,
                                     p17, p18, p19, elen);            // 4 (profiled)
    k_logits<<<dim3(NCHUNK, TL), 256, 98304>>>(p20, target);          // 5
    k_combine<<<TL, 32>>>(target);                                    // 6
    k_out<<<1, 32>>>(out);                                            // 7
}